// round 2
// baseline (speedup 1.0000x reference)
#include <cuda_runtime.h>

// Problem constants
#define BB 4
#define CC 12
#define HH0 512
#define HH1 256              // max H for ping-pong slot 1 (scales 1..4)
#define NBC (BB*CC)          // 48
#define NSCALES 5
#define TS 32                // output tile side
#define NTHR 256

// Slot 0: scales 0, 2, 4 (H = 512, 128, 32). Slot 1: scales 1, 3 (H = 256, 64).
__device__ float g_x0[(size_t)NBC*HH0*HH0];
__device__ float g_y0[(size_t)NBC*HH0*HH0];
__device__ float g_x1[(size_t)NBC*HH1*HH1];
__device__ float g_y1[(size_t)NBC*HH1*HH1];
__device__ float g_ss[NSCALES*NBC];
__device__ float g_cs[NSCALES*NBC];

__constant__ float d_C1 = 0.0001f;   // (0.01)^2
__constant__ float d_C2 = 0.0009f;   // (0.03)^2

__device__ __forceinline__ float* slot_x(int s) { return s ? g_x1 : g_x0; }
__device__ __forceinline__ float* slot_y(int s) { return s ? g_y1 : g_y0; }

// ---------------------------------------------------------------------------
__global__ void zero_acc() {
    int t = threadIdx.x;
    if (t < NSCALES*NBC) { g_ss[t] = 0.f; g_cs[t] = 0.f; }
}

// ---------------------------------------------------------------------------
// Softmax over C plus one-hot of target, written into slot 0.
__global__ __launch_bounds__(256) void softmax_onehot(
    const float* __restrict__ pred, const int* __restrict__ tgt)
{
    const int HW = HH0*HH0;
    int p = blockIdx.x*blockDim.x + threadIdx.x;
    if (p >= BB*HW) return;
    int b  = p / HW;
    int hw = p - b*HW;
    const float* pp = pred + (size_t)b*CC*HW + hw;

    float v[CC];
    float mx = -1e30f;
#pragma unroll
    for (int c = 0; c < CC; c++) { v[c] = pp[(size_t)c*HW]; mx = fmaxf(mx, v[c]); }
    float s = 0.f;
#pragma unroll
    for (int c = 0; c < CC; c++) { v[c] = expf(v[c]-mx); s += v[c]; }
    float inv = 1.f/s;
    int t = tgt[p];
    size_t base = (size_t)b*CC*HW + hw;
#pragma unroll
    for (int c = 0; c < CC; c++) {
        g_x0[base + (size_t)c*HW] = v[c]*inv;
        g_y0[base + (size_t)c*HW] = (c == t) ? 1.f : 0.f;
    }
}

// ---------------------------------------------------------------------------
// 2x2 average pool, slot -> slot. which: 0 = x, 1 = y.
__global__ __launch_bounds__(256) void pool2(int src, int dst, int Hs, int which)
{
    int Hd = Hs >> 1;
    int N  = NBC * Hd * Hd;
    int i = blockIdx.x*blockDim.x + threadIdx.x;
    if (i >= N) return;
    int w  = i % Hd;
    int h  = (i / Hd) % Hd;
    int bc = i / (Hd*Hd);
    const float* S = which ? slot_y(src) : slot_x(src);
    float*       D = which ? slot_y(dst) : slot_x(dst);
    const float* sp = S + (size_t)bc*Hs*Hs;
    float a = sp[(size_t)(2*h)*Hs + 2*w]     + sp[(size_t)(2*h)*Hs + 2*w + 1]
            + sp[(size_t)(2*h+1)*Hs + 2*w]   + sp[(size_t)(2*h+1)*Hs + 2*w + 1];
    D[(size_t)bc*Hd*Hd + (size_t)h*Hd + w] = a*0.25f;
}

// ---------------------------------------------------------------------------
// Tiled separable SSIM: loads a (TS+10)^2 x/y tile, horizontal blur of the 5
// fields {x, y, x^2, y^2, xy}, vertical blur + SSIM map + block reduction.
__global__ __launch_bounds__(NTHR) void ssim_kernel(int slot, int Hs, int sidx)
{
    const int OH = Hs - 10;
    __shared__ float sx[TS+10][TS+10];
    __shared__ float sy[TS+10][TS+10];
    __shared__ float hb[5][TS+10][TS];
    __shared__ float rss[NTHR/32], rcs[NTHR/32];

    // Gaussian weights (win=11, sigma=1.5), normalized — matches reference fp32.
    float gw[11];
    {
        float s = 0.f;
#pragma unroll
        for (int i = 0; i < 11; i++) {
            float d = (float)(i-5);
            gw[i] = expf(-(d*d)/4.5f);
            s += gw[i];
        }
        float inv = 1.f/s;
#pragma unroll
        for (int i = 0; i < 11; i++) gw[i] *= inv;
    }

    int bc  = blockIdx.z;
    int ty0 = blockIdx.y*TS, tx0 = blockIdx.x*TS;
    const float* xp = slot_x(slot) + (size_t)bc*Hs*Hs;
    const float* yp = slot_y(slot) + (size_t)bc*Hs*Hs;
    int tid = threadIdx.x;

    // Load input tile (zero-fill out of range; those outputs are masked later).
    for (int i = tid; i < (TS+10)*(TS+10); i += NTHR) {
        int r = i / (TS+10), c = i - r*(TS+10);
        int ih = ty0 + r, iw = tx0 + c;
        float xv = 0.f, yv = 0.f;
        if (ih < Hs && iw < Hs) {
            size_t o = (size_t)ih*Hs + iw;
            xv = xp[o]; yv = yp[o];
        }
        sx[r][c] = xv; sy[r][c] = yv;
    }
    __syncthreads();

    // Horizontal blur of the 5 fields.
    for (int i = tid; i < (TS+10)*TS; i += NTHR) {
        int r = i / TS, c = i - r*TS;
        float hx=0.f, hy=0.f, hxx=0.f, hyy=0.f, hxy=0.f;
#pragma unroll
        for (int k = 0; k < 11; k++) {
            float g  = gw[k];
            float xv = sx[r][c+k];
            float yv = sy[r][c+k];
            hx  = fmaf(g, xv, hx);
            hy  = fmaf(g, yv, hy);
            hxx = fmaf(g*xv, xv, hxx);
            hyy = fmaf(g*yv, yv, hyy);
            hxy = fmaf(g*xv, yv, hxy);
        }
        hb[0][r][c]=hx; hb[1][r][c]=hy; hb[2][r][c]=hxx; hb[3][r][c]=hyy; hb[4][r][c]=hxy;
    }
    __syncthreads();

    // Vertical blur + SSIM map, thread-local accumulation.
    float lss = 0.f, lcs = 0.f;
    for (int i = tid; i < TS*TS; i += NTHR) {
        int r = i / TS, c = i - r*TS;
        int oh = ty0 + r, ow = tx0 + c;
        if (oh < OH && ow < OH) {
            float m1=0.f, m2=0.f, e11=0.f, e22=0.f, e12=0.f;
#pragma unroll
            for (int k = 0; k < 11; k++) {
                float g = gw[k];
                m1  = fmaf(g, hb[0][r+k][c], m1);
                m2  = fmaf(g, hb[1][r+k][c], m2);
                e11 = fmaf(g, hb[2][r+k][c], e11);
                e22 = fmaf(g, hb[3][r+k][c], e22);
                e12 = fmaf(g, hb[4][r+k][c], e12);
            }
            float m11 = m1*m1, m22 = m2*m2, m12 = m1*m2;
            float v1  = e11 - m11, v2 = e22 - m22, cov = e12 - m12;
            float cs  = (2.f*cov + d_C2) / (v1 + v2 + d_C2);
            float ss  = (2.f*m12 + d_C1) / (m11 + m22 + d_C1) * cs;
            lss += ss; lcs += cs;
        }
    }

    // Block reduction -> atomicAdd into per-(scale, b*C+c) accumulators.
#pragma unroll
    for (int o = 16; o; o >>= 1) {
        lss += __shfl_down_sync(0xffffffffu, lss, o);
        lcs += __shfl_down_sync(0xffffffffu, lcs, o);
    }
    if ((tid & 31) == 0) { rss[tid>>5] = lss; rcs[tid>>5] = lcs; }
    __syncthreads();
    if (tid == 0) {
        float ts = 0.f, tc = 0.f;
#pragma unroll
        for (int w = 0; w < NTHR/32; w++) { ts += rss[w]; tc += rcs[w]; }
        atomicAdd(&g_ss[sidx*NBC + bc], ts);
        atomicAdd(&g_cs[sidx*NBC + bc], tc);
    }
}

// ---------------------------------------------------------------------------
__global__ void finalize(float* __restrict__ out)
{
    __shared__ float sm[NBC];
    int t = threadIdx.x;
    const float Wt[5] = {0.0448f, 0.2856f, 0.3001f, 0.2363f, 0.1333f};
    // valid spatial counts per scale: (H_s - 10)^2
    const float cnt[5] = {502.f*502.f, 246.f*246.f, 118.f*118.f, 54.f*54.f, 22.f*22.f};
    if (t < NBC) {
        float ms = 1.f;
#pragma unroll
        for (int s = 0; s < NSCALES; s++) {
            float acc = (s == NSCALES-1) ? g_ss[s*NBC + t] : g_cs[s*NBC + t];
            float v = acc / cnt[s];
            v = fmaxf(v, 0.f);
            ms *= powf(v, Wt[s]);
        }
        sm[t] = ms;
    }
    __syncthreads();
    if (t == 0) {
        float a = 0.f;
#pragma unroll
        for (int i = 0; i < NBC; i++) a += sm[i];
        out[0] = 1.f - a / (float)NBC;
    }
}

// ---------------------------------------------------------------------------
extern "C" void kernel_launch(void* const* d_in, const int* in_sizes, int n_in,
                              void* d_out, int out_size)
{
    const float* pred = (const float*)d_in[0];
    const int*   tgt  = (const int*)d_in[1];
    float*       out  = (float*)d_out;

    zero_acc<<<1, 256>>>();

    int np = BB*HH0*HH0;
    softmax_onehot<<<(np + 255)/256, 256>>>(pred, tgt);

    int Hs = HH0;
    for (int s = 0; s < NSCALES; s++) {
        if (s > 0) {
            int src = (s-1) & 1, dst = s & 1;
            int Hd = Hs >> 1;
            int N  = NBC*Hd*Hd;
            pool2<<<(N + 255)/256, 256>>>(src, dst, Hs, 0);
            pool2<<<(N + 255)/256, 256>>>(src, dst, Hs, 1);
            Hs = Hd;
        }
        int slot = s & 1;
        int OH = Hs - 10;
        int nt = (OH + TS - 1)/TS;
        dim3 grid(nt, nt, NBC);
        ssim_kernel<<<grid, NTHR>>>(slot, Hs, s);
    }

    finalize<<<1, 64>>>(out);
}